// round 14
// baseline (speedup 1.0000x reference)
#include <cuda_runtime.h>
#include <cuda_fp16.h>

// EgoAttentionNetwork: B=8192, E=64, F_IN=7, D=64, H=4, HD=16
// Round-13 = Round-12 minus the K and V GEMMs, via single-query algebra:
//   scores = Ah1 @ (Wk q)          (Z: 4x64, tiny)
//   out    = (P^T Ah1) @ (Wv Wc)   (u: 4x64; G = per-head Wv*Wc, prep-folded)
// Only layer0 + layer1 remain on HMMA. No fast/slow split; loops run to Mpad.

typedef unsigned int u32;

#define NTHR 256
#define FULLMASK 0xffffffffu
#define AXS 24     // Axh row stride in halves (48B: conflict-free ldsm)
#define AHS 72     // Ah0/Ah1 row stride in halves (144B)

__device__ uint2   dF0[256];     // oth_w0 B-fragments [nt(8)][lane], k padded to 16
__device__ uint2   dF1[1024];    // oth_w1 B-fragments [kt(4)][nt(8)][lane]
__device__ __half2 dKp[2048];    // Wk d-pair packed: dKp[dp*64+k] = (Wk[k][2dp],Wk[k][2dp+1])
__device__ __half2 dGp[8192];    // G j-pair packed: dGp[jp*64+c] = (G[2jp][c],G[2jp+1][c])
__device__ __half2 dW1ep[2048];  // ego_w1 k-pair packed
__device__ __half2 dWqp[2048];   // Wq k-pair packed

static __device__ __forceinline__ unsigned int f2h2(float a, float b) {
    __half2 h = __floats2half2_rn(a, b);
    return *reinterpret_cast<unsigned int*>(&h);
}
static __device__ __forceinline__ float2 h2fp(const __half2* p) {
    return __half22float2(*p);
}
static __device__ __forceinline__ u32 s2u(const void* p) {
    return (u32)__cvta_generic_to_shared(p);
}
static __device__ __forceinline__ void ldsm4(u32* a, u32 addr) {
    asm volatile("ldmatrix.sync.aligned.m8n8.x4.shared.b16 {%0,%1,%2,%3}, [%4];"
                 : "=r"(a[0]), "=r"(a[1]), "=r"(a[2]), "=r"(a[3]) : "r"(addr));
}
static __device__ __forceinline__ void mma16816(
    float& c0, float& c1, float& c2, float& c3,
    const u32* a, u32 b0, u32 b1)
{
    asm volatile(
        "mma.sync.aligned.m16n8k16.row.col.f32.f16.f16.f32 "
        "{%0,%1,%2,%3}, {%4,%5,%6,%7}, {%8,%9}, {%0,%1,%2,%3};"
        : "+f"(c0), "+f"(c1), "+f"(c2), "+f"(c3)
        : "r"(a[0]), "r"(a[1]), "r"(a[2]), "r"(a[3]), "r"(b0), "r"(b1));
}

__device__ __forceinline__ u32 pkw(const float* W, int k, int n) {
    return f2h2(__ldg(W + k * 64 + n), __ldg(W + (k + 1) * 64 + n));
}
__device__ __forceinline__ u32 pkw7(const float* W, int k, int n) {
    float a = (k < 7) ? __ldg(W + k * 64 + n) : 0.f;
    float b = (k + 1 < 7) ? __ldg(W + (k + 1) * 64 + n) : 0.f;
    return f2h2(a, b);
}
__device__ __forceinline__ float gentry(const float* Wv, const float* Wc,
                                        int j, int c) {
    const int h = j >> 6, k = j & 63;
    float acc = 0.f;
    #pragma unroll
    for (int dd = 0; dd < 16; dd++) {
        int d = h * 16 + dd;
        acc += __ldg(Wv + k * 64 + d) * __ldg(Wc + d * 64 + c);
    }
    return acc;
}

__global__ void prep_weights(const float* __restrict__ oth_w0,
                             const float* __restrict__ oth_w1,
                             const float* __restrict__ Wk,
                             const float* __restrict__ Wv,
                             const float* __restrict__ ego_w1,
                             const float* __restrict__ Wq,
                             const float* __restrict__ Wc)
{
    const int i = blockIdx.x * 256 + threadIdx.x;   // 0..8191
    const int lane = i & 31;
    if (i < 256) {
        const int nt = i >> 5;
        const int n = nt * 8 + (lane >> 2);
        const int k = (lane & 3) * 2;
        dF0[i] = make_uint2(pkw7(oth_w0, k, n), pkw7(oth_w0, k + 8, n));
    }
    if (i < 1024) {
        const int nt = (i >> 5) & 7, kt = i >> 8;
        const int n = nt * 8 + (lane >> 2);
        const int k = kt * 16 + (lane & 3) * 2;
        dF1[i] = make_uint2(pkw(oth_w1, k, n), pkw(oth_w1, k + 8, n));
    }
    if (i < 2048) {
        {   // dKp[dp*64+k]
            const int dp = i >> 6, k = i & 63;
            dKp[i] = __floats2half2_rn(__ldg(Wk + k * 64 + 2 * dp),
                                       __ldg(Wk + k * 64 + 2 * dp + 1));
        }
        {   // k-pair packed side matrices
            const int kp = i >> 6, d = i & 63;
            const int k0 = 2 * kp * 64 + d, k1 = (2 * kp + 1) * 64 + d;
            dW1ep[i] = __floats2half2_rn(__ldg(ego_w1 + k0), __ldg(ego_w1 + k1));
            dWqp[i]  = __floats2half2_rn(__ldg(Wq + k0),     __ldg(Wq + k1));
        }
    }
    {   // dGp[jp*64+c]
        const int jp = i >> 6, c = i & 63;
        dGp[i] = __floats2half2_rn(gentry(Wv, Wc, 2 * jp, c),
                                   gentry(Wv, Wc, 2 * jp + 1, c));
    }
}

struct __align__(16) SmemT {
    __half Axh[64 * AXS];    // fp16 compacted x rows (k padded to 16)
    __half Ah0[64 * AHS];    // hidden (layer0 out)
    __half Ah1[64 * AHS];    // input_all (layer1 out)
    float  sX[64 * 8];       // fp32 raw x
    float  h0[64];
    float  sEgo[64];
    float  sQ[64];
    float  sZ[256];          // Z[h*64+k]
    float  sU[256];          // u[h*64+k]
    float  sS[256];          // scores; reused as final partials
    float  sP[256];
    int    sIdx[64];
    int    nOth, uniformF, egoAct;
};

__global__ void __launch_bounds__(NTHR, 4)
ego_attn_kernel(const float* __restrict__ x,
                const float* __restrict__ ego_w0, const float* __restrict__ ego_b0,
                const float* __restrict__ ego_b1,
                const float* __restrict__ oth_b0, const float* __restrict__ oth_b1,
                float* __restrict__ out)
{
    __shared__ SmemT s;
    const int tid = threadIdx.x;
    const int lane = tid & 31;
    const int w = tid >> 5;
    const int mt = w & 1;        // m16 tile within a 32-row pass
    const int g = w >> 1;        // n-tile pair owner
    const long b = blockIdx.x;
    const float* xb = x + b * 448;
    const int col0 = (lane & 3) * 2;

    // ---- PH1: load x; init score buffer ----
    for (int idx = tid; idx < 448; idx += NTHR) {
        int e = idx / 7, f = idx - (idx / 7) * 7;
        s.sX[e * 8 + f] = __ldg(xb + idx);
    }
    s.sS[tid] = -1e30f;
    __syncthreads();

    // ---- PH2: compaction (warp0) | ego layer0 (warp1) ----
    if (tid < 32) {
        int egoA = (s.sX[0] >= 0.5f) ? 1 : 0;
        unsigned m1 = __ballot_sync(FULLMASK, (lane >= 1) && (s.sX[lane * 8] >= 0.5f));
        unsigned m2 = __ballot_sync(FULLMASK, s.sX[(lane + 32) * 8] >= 0.5f);
        int cnt = __popc(m1) + __popc(m2);
        unsigned lmask = (1u << lane) - 1u;
        if (cnt == 0 && !egoA) {
            s.sIdx[lane] = lane + 1;
            if (lane < 31) s.sIdx[lane + 32] = lane + 33;
            if (lane == 0) { s.nOth = 63; s.uniformF = 1; s.egoAct = egoA; }
        } else {
            if ((lane >= 1) && (m1 >> lane & 1u))
                s.sIdx[__popc(m1 & lmask)] = lane;
            if (m2 >> lane & 1u)
                s.sIdx[__popc(m1) + __popc(m2 & lmask)] = lane + 32;
            if (lane == 0) { s.nOth = cnt; s.uniformF = 0; s.egoAct = egoA; }
        }
    } else if (tid < 64) {
        const int ln = tid - 32;
        #pragma unroll
        for (int r = 0; r < 2; r++) {
            int d = ln + r * 32;
            float acc = __ldg(ego_b0 + d);
            #pragma unroll
            for (int f = 0; f < 7; f++)
                acc += s.sX[f] * __ldg(ego_w0 + f * 64 + d);
            s.h0[d] = fmaxf(acc, 0.f);
        }
    }
    __syncthreads();

    const int nOth = s.nOth;
    const int uniformF = s.uniformF;
    const int egoAct = s.egoAct;
    const int cEgo = nOth;
    const int nTot = nOth + 1;
    const int Mpad = (nTot <= 32) ? 32 : 64;
    const int npass = Mpad >> 5;

    // ---- PH3: gather compacted x -> Axh fp16 (thr 0-63) | ego layer1 ----
    if (tid < 64) {
        const int row = tid;
        if (row < Mpad) {
            __half2* dst = reinterpret_cast<__half2*>(s.Axh + row * AXS);
            const __half2 z2 = __floats2half2_rn(0.f, 0.f);
            if (row < nOth) {
                const float* xr = s.sX + s.sIdx[row] * 8;
                dst[0] = __floats2half2_rn(xr[0], xr[1]);
                dst[1] = __floats2half2_rn(xr[2], xr[3]);
                dst[2] = __floats2half2_rn(xr[4], xr[5]);
                dst[3] = __floats2half2_rn(xr[6], 0.f);
                dst[4] = z2; dst[5] = z2; dst[6] = z2; dst[7] = z2;
            } else {
                #pragma unroll
                for (int i = 0; i < 8; i++) dst[i] = z2;
            }
        }
    } else if (tid >= 192) {
        const int d = tid - 192;
        float a0 = __ldg(ego_b1 + d), a1 = 0.f;
        #pragma unroll 8
        for (int kp = 0; kp < 32; kp++) {
            float2 wv = h2fp(&dW1ep[kp * 64 + d]);
            float2 hv = *reinterpret_cast<const float2*>(&s.h0[2 * kp]);
            a0 += hv.x * wv.x;
            a1 += hv.y * wv.y;
        }
        s.sEgo[d] = fmaxf(a0 + a1, 0.f);
    }
    __syncthreads();

    // ---- PH4: layer0 HMMA (k16): Axh -> Ah0 (bias+relu) ----
    for (int mp = 0; mp < npass; mp++) {
        const int m_base = mp * 32 + mt * 16;
        u32 A[4];
        u32 ab = s2u(s.Axh + (m_base + (lane & 15)) * AXS + ((lane >> 4) << 3));
        ldsm4(A, ab);
        const int r0 = m_base + (lane >> 2), r1 = r0 + 8;
        #pragma unroll
        for (int nt2 = 0; nt2 < 2; nt2++) {
            const int nt = g * 2 + nt2;
            const int cA = nt * 8 + col0;
            uint2 bf = __ldg(&dF0[nt * 32 + lane]);
            float c0 = __ldg(oth_b0 + cA), c1 = __ldg(oth_b0 + cA + 1);
            float c2 = c0, c3 = c1;
            mma16816(c0, c1, c2, c3, A, bf.x, bf.y);
            *reinterpret_cast<__half2*>(&s.Ah0[r0 * AHS + cA]) =
                __floats2half2_rn(fmaxf(c0, 0.f), fmaxf(c1, 0.f));
            *reinterpret_cast<__half2*>(&s.Ah0[r1 * AHS + cA]) =
                __floats2half2_rn(fmaxf(c2, 0.f), fmaxf(c3, 0.f));
        }
    }
    __syncthreads();

    // ---- PH5: layer1 HMMA: Ah0 -> Ah1 (bias+relu+ego patch); then q ----
    for (int mp = 0; mp < npass; mp++) {
        const int m_base = mp * 32 + mt * 16;
        u32 A[4][4];
        u32 ab = s2u(s.Ah0 + (m_base + (lane & 15)) * AHS + ((lane >> 4) << 3));
        #pragma unroll
        for (int kt = 0; kt < 4; kt++) ldsm4(A[kt], ab + kt * 32);
        const int r0 = m_base + (lane >> 2), r1 = r0 + 8;
        #pragma unroll
        for (int nt2 = 0; nt2 < 2; nt2++) {
            const int nt = g * 2 + nt2;
            const int cA = nt * 8 + col0;
            float c0 = __ldg(oth_b1 + cA), c1 = __ldg(oth_b1 + cA + 1);
            float c2 = c0, c3 = c1;
            #pragma unroll
            for (int kt = 0; kt < 4; kt++) {
                uint2 bf = __ldg(&dF1[(kt * 8 + nt) * 32 + lane]);
                mma16816(c0, c1, c2, c3, A[kt], bf.x, bf.y);
            }
            c0 = fmaxf(c0, 0.f); c1 = fmaxf(c1, 0.f);
            c2 = fmaxf(c2, 0.f); c3 = fmaxf(c3, 0.f);
            if (r0 == cEgo) { c0 = s.sEgo[cA]; c1 = s.sEgo[cA + 1]; }
            if (r1 == cEgo) { c2 = s.sEgo[cA]; c3 = s.sEgo[cA + 1]; }
            *reinterpret_cast<__half2*>(&s.Ah1[r0 * AHS + cA]) =
                __floats2half2_rn(c0, c1);
            *reinterpret_cast<__half2*>(&s.Ah1[r1 * AHS + cA]) =
                __floats2half2_rn(c2, c3);
        }
    }
    if (tid < 64) {
        const int d = tid;
        float a0 = 0.f, a1 = 0.f;
        #pragma unroll 8
        for (int kp = 0; kp < 32; kp++) {
            float2 wv = h2fp(&dWqp[kp * 64 + d]);
            float2 ev = *reinterpret_cast<const float2*>(&s.sEgo[2 * kp]);
            a0 += ev.x * wv.x;
            a1 += ev.y * wv.y;
        }
        s.sQ[d] = a0 + a1;
    }
    __syncthreads();

    // ---- PH6a: Z[h][k] = 0.25 * sum_{d in h} Wk[k][d] q[d]  (256 thr) ----
    {
        const int k = tid & 63, h = tid >> 6;
        const float* qh = s.sQ + h * 16;
        float acc = 0.f;
        #pragma unroll
        for (int jj = 0; jj < 8; jj++) {
            float2 wv = h2fp(&dKp[(h * 8 + jj) * 64 + k]);
            float2 qv = *reinterpret_cast<const float2*>(&qh[2 * jj]);
            acc += qv.x * wv.x + qv.y * wv.y;
        }
        s.sZ[tid] = acc * 0.25f;
    }
    __syncthreads();

    // ---- PH6b: scores[e][h] = Ah1[e,:] . Z[:,h]  (128 thr per chunk) ----
    if (tid < 128) {
        const int h = tid & 3;
        for (int ch = 0; ch < npass; ch++) {
            const int e = ch * 32 + (tid >> 2);
            const __half2* ar = reinterpret_cast<const __half2*>(&s.Ah1[e * AHS]);
            const float2* zr = reinterpret_cast<const float2*>(&s.sZ[h * 64]);
            float a0 = 0.f, a1 = 0.f;
            #pragma unroll 8
            for (int kp = 0; kp < 32; kp++) {
                float2 a = __half22float2(ar[kp]);
                float2 z = zr[kp];
                a0 += a.x * z.x;
                a1 += a.y * z.y;
            }
            bool act = uniformF ? (e < nTot)
                                : ((e < nOth) || (e == cEgo && egoAct));
            s.sS[h * 64 + e] = act ? (a0 + a1) : -1e30f;
        }
    }
    __syncthreads();

    // ---- PH7: softmax per head (warps 0-3) ----
    if (tid < 128) {
        const int h = tid >> 5, ln = tid & 31;
        if (uniformF) {
            const float p = 1.0f / 64.0f;
            s.sP[h * 64 + ln] = p;
            s.sP[h * 64 + ln + 32] = p;
        } else {
            float s0 = s.sS[h * 64 + ln];
            float s1 = s.sS[h * 64 + ln + 32];
            float m = fmaxf(s0, s1);
            #pragma unroll
            for (int off = 16; off; off >>= 1)
                m = fmaxf(m, __shfl_xor_sync(FULLMASK, m, off));
            float e0 = __expf(s0 - m);
            float e1 = __expf(s1 - m);
            float sum = e0 + e1;
            #pragma unroll
            for (int off = 16; off; off >>= 1)
                sum += __shfl_xor_sync(FULLMASK, sum, off);
            float inv = 1.0f / sum;
            s.sP[h * 64 + ln] = e0 * inv;
            s.sP[h * 64 + ln + 32] = e1 * inv;
        }
    }
    __syncthreads();

    // ---- PH8: u[h][k] = sum_e p_h[e] * Ah1[e][k]  (256 thr) ----
    {
        const int k = tid & 63, h = tid >> 6;
        float acc = 0.f;
        #pragma unroll 8
        for (int e = 0; e < Mpad; e++) {
            float p = s.sP[h * 64 + e];
            float a = __half2float(s.Ah1[e * AHS + k]);
            acc += p * a;
        }
        s.sU[tid] = acc;
    }
    __syncthreads();

    // ---- PH9: out[c] = (sum_j u[j] G[j][c] + ego[c]) * 0.5  (256 thr) ----
    {
        const int c = tid & 63, q4 = tid >> 6;
        const float2* up = reinterpret_cast<const float2*>(&s.sU[q4 * 64]);
        float a0 = 0.f, a1 = 0.f;
        #pragma unroll 8
        for (int jp = 0; jp < 32; jp++) {
            float2 gv = h2fp(&dGp[(q4 * 32 + jp) * 64 + c]);
            float2 uv = up[jp];
            a0 += uv.x * gv.x;
            a1 += uv.y * gv.y;
        }
        s.sS[tid] = a0 + a1;     // sS reused as partials
    }
    __syncthreads();
    if (tid < 64) {
        float v = s.sS[tid] + s.sS[64 + tid] + s.sS[128 + tid] + s.sS[192 + tid];
        out[b * 64 + tid] = (v + s.sEgo[tid]) * 0.5f;
    }
}

extern "C" void kernel_launch(void* const* d_in, const int* in_sizes, int n_in,
                              void* d_out, int out_size) {
    (void)in_sizes; (void)n_in; (void)out_size;
    const float* x      = (const float*)d_in[0];
    const float* ego_w0 = (const float*)d_in[1];
    const float* ego_b0 = (const float*)d_in[2];
    const float* ego_w1 = (const float*)d_in[3];
    const float* ego_b1 = (const float*)d_in[4];
    const float* oth_w0 = (const float*)d_in[5];
    const float* oth_b0 = (const float*)d_in[6];
    const float* oth_w1 = (const float*)d_in[7];
    const float* oth_b1 = (const float*)d_in[8];
    const float* Wk     = (const float*)d_in[9];
    const float* Wv     = (const float*)d_in[10];
    const float* Wq     = (const float*)d_in[11];
    const float* Wc     = (const float*)d_in[12];
    float* out = (float*)d_out;

    prep_weights<<<32, 256>>>(oth_w0, oth_w1, Wk, Wv, ego_w1, Wq, Wc);
    ego_attn_kernel<<<8192, NTHR>>>(x, ego_w0, ego_b0, ego_b1,
                                    oth_b0, oth_b1, out);
}

// round 15
// speedup vs baseline: 1.8069x; 1.8069x over previous
#include <cuda_runtime.h>
#include <cuda_fp16.h>

// EgoAttentionNetwork: B=8192, E=64, F_IN=7, D=64, H=4, HD=16
// Round-14 = Round-12 dataflow (best 78.6us) remapped to 128-thread CTAs with
// warp = head. Each warp covers all M rows (mt loop), so scores/softmax/P.V
// are fully warp-local (no barriers, no sS/sP smem, no atomics), B-fragments
// load once per warp, and 8 CTAs fit per SM for latency hiding.

typedef unsigned int u32;

#define NTHR 128
#define FULLMASK 0xffffffffu
#define AXS 24     // Axh row stride in halves (48B: conflict-free ldsm)
#define AHS 72     // Ah0/Ah1 row stride in halves (144B)

__device__ uint2   dF0[256];     // oth_w0 B-fragments [nt(8)][lane], k padded to 16
__device__ uint2   dF1[1024];    // oth_w1 B-fragments [kt(4)][nt(8)][lane]
__device__ uint2   dFk[1024];    // Wk fragments
__device__ uint2   dFv[1024];    // Wv fragments
__device__ __half2 dW1ep[2048];  // ego_w1 k-pair packed
__device__ __half2 dWqp[2048];   // Wq k-pair packed
__device__ __half2 dWcp[2048];   // Wc k-pair packed

static __device__ __forceinline__ unsigned int f2h2(float a, float b) {
    __half2 h = __floats2half2_rn(a, b);
    return *reinterpret_cast<unsigned int*>(&h);
}
static __device__ __forceinline__ u32 s2u(const void* p) {
    return (u32)__cvta_generic_to_shared(p);
}
static __device__ __forceinline__ void ldsm4(u32* a, u32 addr) {
    asm volatile("ldmatrix.sync.aligned.m8n8.x4.shared.b16 {%0,%1,%2,%3}, [%4];"
                 : "=r"(a[0]), "=r"(a[1]), "=r"(a[2]), "=r"(a[3]) : "r"(addr));
}
static __device__ __forceinline__ void mma16816(
    float& c0, float& c1, float& c2, float& c3,
    const u32* a, u32 b0, u32 b1)
{
    asm volatile(
        "mma.sync.aligned.m16n8k16.row.col.f32.f16.f16.f32 "
        "{%0,%1,%2,%3}, {%4,%5,%6,%7}, {%8,%9}, {%0,%1,%2,%3};"
        : "+f"(c0), "+f"(c1), "+f"(c2), "+f"(c3)
        : "r"(a[0]), "r"(a[1]), "r"(a[2]), "r"(a[3]), "r"(b0), "r"(b1));
}

__device__ __forceinline__ u32 pkw(const float* W, int k, int n) {
    return f2h2(__ldg(W + k * 64 + n), __ldg(W + (k + 1) * 64 + n));
}
__device__ __forceinline__ u32 pkw7(const float* W, int k, int n) {
    float a = (k < 7) ? __ldg(W + k * 64 + n) : 0.f;
    float b = (k + 1 < 7) ? __ldg(W + (k + 1) * 64 + n) : 0.f;
    return f2h2(a, b);
}

__global__ void prep_weights(const float* __restrict__ oth_w0,
                             const float* __restrict__ oth_w1,
                             const float* __restrict__ Wk,
                             const float* __restrict__ Wv,
                             const float* __restrict__ ego_w1,
                             const float* __restrict__ Wq,
                             const float* __restrict__ Wc)
{
    const int i = blockIdx.x * 256 + threadIdx.x;   // 0..2047
    const int lane = i & 31;
    if (i < 256) {
        const int nt = i >> 5;
        const int n = nt * 8 + (lane >> 2);
        const int k = (lane & 3) * 2;
        dF0[i] = make_uint2(pkw7(oth_w0, k, n), pkw7(oth_w0, k + 8, n));
    }
    if (i < 1024) {
        const int nt = (i >> 5) & 7, kt = i >> 8;
        const int n = nt * 8 + (lane >> 2);
        const int k = kt * 16 + (lane & 3) * 2;
        dF1[i] = make_uint2(pkw(oth_w1, k, n), pkw(oth_w1, k + 8, n));
        dFk[i] = make_uint2(pkw(Wk, k, n),     pkw(Wk, k + 8, n));
        dFv[i] = make_uint2(pkw(Wv, k, n),     pkw(Wv, k + 8, n));
    }
    {
        const int kp = i >> 6, d = i & 63;
        const int k0 = 2 * kp * 64 + d, k1 = (2 * kp + 1) * 64 + d;
        dW1ep[i] = __floats2half2_rn(__ldg(ego_w1 + k0), __ldg(ego_w1 + k1));
        dWqp[i]  = __floats2half2_rn(__ldg(Wq + k0),     __ldg(Wq + k1));
        dWcp[i]  = __floats2half2_rn(__ldg(Wc + k0),     __ldg(Wc + k1));
    }
}

struct __align__(16) SmemT {
    union {
        __half Axh[64 * AXS];   // fp16 compacted x (live: PH3-PH4)
        __half Ah1[64 * AHS];   // input_all (live: PH5-end)
    } u1;
    __half Ah0[64 * AHS];       // hidden (layer0 out)
    float  sX[64 * 8];
    float  h0[64];
    float  sEgo[64];
    float  sQ[64];
    float  sO[64];
    int    sIdx[64];
    int    nOth, uniformF, egoAct;
};

// K -> in-warp softmax -> V -> P.V (all warp-local). NTM = Mpad/16.
template <int NTM>
__device__ __forceinline__ void attn_tail(SmemT& s, int g, int lane,
                                          int nOth, int cEgo, int egoAct,
                                          int uniformF)
{
    const int col0 = (lane & 3) * 2;
    const int lr = lane >> 2;
    float p[2 * NTM];

    // K phase: scores for all rows of this head
    {
        uint2 bk[2][4];
        #pragma unroll
        for (int nt2 = 0; nt2 < 2; nt2++)
            #pragma unroll
            for (int kt = 0; kt < 4; kt++)
                bk[nt2][kt] = __ldg(&dFk[(kt * 8 + g * 2 + nt2) * 32 + lane]);
        #pragma unroll
        for (int mtl = 0; mtl < NTM; mtl++) {
            u32 A[4][4];
            u32 ab = s2u(s.u1.Ah1 + (mtl * 16 + (lane & 15)) * AHS +
                         ((lane >> 4) << 3));
            #pragma unroll
            for (int kt = 0; kt < 4; kt++) ldsm4(A[kt], ab + kt * 32);
            float p0 = 0.f, p1 = 0.f;
            #pragma unroll
            for (int nt2 = 0; nt2 < 2; nt2++) {
                const int cA = (g * 2 + nt2) * 8 + col0;
                float k0 = 0.f, k1 = 0.f, k2 = 0.f, k3 = 0.f;
                #pragma unroll
                for (int kt = 0; kt < 4; kt++)
                    mma16816(k0, k1, k2, k3, A[kt],
                             bk[nt2][kt].x, bk[nt2][kt].y);
                float q0 = s.sQ[cA], q1 = s.sQ[cA + 1];
                p0 += k0 * q0 + k1 * q1;
                p1 += k2 * q0 + k3 * q1;
            }
            p0 += __shfl_xor_sync(FULLMASK, p0, 1);
            p1 += __shfl_xor_sync(FULLMASK, p1, 1);
            p0 += __shfl_xor_sync(FULLMASK, p0, 2);
            p1 += __shfl_xor_sync(FULLMASK, p1, 2);
            const int e0 = mtl * 16 + lr, e1 = e0 + 8;
            bool a0 = (e0 < nOth) || (e0 == cEgo && egoAct);
            bool a1 = (e1 < nOth) || (e1 == cEgo && egoAct);
            p[2 * mtl]     = a0 ? p0 * 0.25f : -1e30f;
            p[2 * mtl + 1] = a1 ? p1 * 0.25f : -1e30f;
        }
    }

    // in-warp softmax (rows are quad-replicated -> reduce over off 4,8,16)
    if (uniformF) {
        #pragma unroll
        for (int i = 0; i < 2 * NTM; i++) p[i] = 1.0f / 64.0f;
    } else {
        float m = p[0];
        #pragma unroll
        for (int i = 1; i < 2 * NTM; i++) m = fmaxf(m, p[i]);
        #pragma unroll
        for (int off = 4; off < 32; off <<= 1)
            m = fmaxf(m, __shfl_xor_sync(FULLMASK, m, off));
        float sum = 0.f;
        #pragma unroll
        for (int i = 0; i < 2 * NTM; i++) {
            p[i] = __expf(p[i] - m);
            sum += p[i];
        }
        #pragma unroll
        for (int off = 4; off < 32; off <<= 1)
            sum += __shfl_xor_sync(FULLMASK, sum, off);
        float inv = 1.0f / sum;
        #pragma unroll
        for (int i = 0; i < 2 * NTM; i++) p[i] *= inv;
    }

    // V phase + P.V accumulate
    float o00 = 0.f, o01 = 0.f, o10 = 0.f, o11 = 0.f;
    {
        uint2 bv[2][4];
        #pragma unroll
        for (int nt2 = 0; nt2 < 2; nt2++)
            #pragma unroll
            for (int kt = 0; kt < 4; kt++)
                bv[nt2][kt] = __ldg(&dFv[(kt * 8 + g * 2 + nt2) * 32 + lane]);
        #pragma unroll
        for (int mtl = 0; mtl < NTM; mtl++) {
            u32 A[4][4];
            u32 ab = s2u(s.u1.Ah1 + (mtl * 16 + (lane & 15)) * AHS +
                         ((lane >> 4) << 3));
            #pragma unroll
            for (int kt = 0; kt < 4; kt++) ldsm4(A[kt], ab + kt * 32);
            const float pr0 = p[2 * mtl], pr1 = p[2 * mtl + 1];
            {
                float v0 = 0.f, v1 = 0.f, v2 = 0.f, v3 = 0.f;
                #pragma unroll
                for (int kt = 0; kt < 4; kt++)
                    mma16816(v0, v1, v2, v3, A[kt],
                             bv[0][kt].x, bv[0][kt].y);
                o00 += pr0 * v0 + pr1 * v2;
                o01 += pr0 * v1 + pr1 * v3;
            }
            {
                float v0 = 0.f, v1 = 0.f, v2 = 0.f, v3 = 0.f;
                #pragma unroll
                for (int kt = 0; kt < 4; kt++)
                    mma16816(v0, v1, v2, v3, A[kt],
                             bv[1][kt].x, bv[1][kt].y);
                o10 += pr0 * v0 + pr1 * v2;
                o11 += pr0 * v1 + pr1 * v3;
            }
        }
    }
    #pragma unroll
    for (int off = 4; off < 32; off <<= 1) {
        o00 += __shfl_xor_sync(FULLMASK, o00, off);
        o01 += __shfl_xor_sync(FULLMASK, o01, off);
        o10 += __shfl_xor_sync(FULLMASK, o10, off);
        o11 += __shfl_xor_sync(FULLMASK, o11, off);
    }
    if (lane < 4) {
        s.sO[(g * 2)     * 8 + lane * 2]     = o00;
        s.sO[(g * 2)     * 8 + lane * 2 + 1] = o01;
        s.sO[(g * 2 + 1) * 8 + lane * 2]     = o10;
        s.sO[(g * 2 + 1) * 8 + lane * 2 + 1] = o11;
    }
}

__global__ void __launch_bounds__(NTHR, 8)
ego_attn_kernel(const float* __restrict__ x,
                const float* __restrict__ ego_w0, const float* __restrict__ ego_b0,
                const float* __restrict__ ego_b1,
                const float* __restrict__ oth_b0, const float* __restrict__ oth_b1,
                float* __restrict__ out)
{
    __shared__ SmemT s;
    const int tid = threadIdx.x;
    const int lane = tid & 31;
    const int g = tid >> 5;      // warp = head
    const long b = blockIdx.x;
    const float* xb = x + b * 448;
    const int col0 = (lane & 3) * 2;
    const int lr = lane >> 2;

    // ---- PH1: load x ----
    for (int idx = tid; idx < 448; idx += NTHR) {
        int e = idx / 7, f = idx - (idx / 7) * 7;
        s.sX[e * 8 + f] = __ldg(xb + idx);
    }
    __syncthreads();

    // ---- PH2: compaction (warp0) | ego layer0 (warp1) ----
    if (g == 0) {
        int egoA = (s.sX[0] >= 0.5f) ? 1 : 0;
        unsigned m1 = __ballot_sync(FULLMASK, (lane >= 1) && (s.sX[lane * 8] >= 0.5f));
        unsigned m2 = __ballot_sync(FULLMASK, s.sX[(lane + 32) * 8] >= 0.5f);
        int cnt = __popc(m1) + __popc(m2);
        unsigned lmask = (1u << lane) - 1u;
        if (cnt == 0 && !egoA) {
            s.sIdx[lane] = lane + 1;
            if (lane < 31) s.sIdx[lane + 32] = lane + 33;
            if (lane == 0) { s.nOth = 63; s.uniformF = 1; s.egoAct = egoA; }
        } else {
            if ((lane >= 1) && (m1 >> lane & 1u))
                s.sIdx[__popc(m1 & lmask)] = lane;
            if (m2 >> lane & 1u)
                s.sIdx[__popc(m1) + __popc(m2 & lmask)] = lane + 32;
            if (lane == 0) { s.nOth = cnt; s.uniformF = 0; s.egoAct = egoA; }
        }
    } else if (g == 1) {
        #pragma unroll
        for (int r = 0; r < 2; r++) {
            int d = lane + r * 32;
            float acc = __ldg(ego_b0 + d);
            #pragma unroll
            for (int f = 0; f < 7; f++)
                acc += s.sX[f] * __ldg(ego_w0 + f * 64 + d);
            s.h0[d] = fmaxf(acc, 0.f);
        }
    }
    __syncthreads();

    const int nOth = s.nOth;
    const int uniformF = s.uniformF;
    const int egoAct = s.egoAct;
    const int cEgo = nOth;
    const int nTot = nOth + 1;
    const int Mpad = (nTot <= 32) ? 32 : 64;
    const int ntm = Mpad >> 4;

    // ---- PH3: gather compacted x -> Axh fp16 (thr 0-63) | ego layer1 ----
    if (tid < 64) {
        const int row = tid;
        if (row < Mpad) {
            __half2* dst = reinterpret_cast<__half2*>(s.u1.Axh + row * AXS);
            const __half2 z2 = __floats2half2_rn(0.f, 0.f);
            if (row < nOth) {
                const float* xr = s.sX + s.sIdx[row] * 8;
                dst[0] = __floats2half2_rn(xr[0], xr[1]);
                dst[1] = __floats2half2_rn(xr[2], xr[3]);
                dst[2] = __floats2half2_rn(xr[4], xr[5]);
                dst[3] = __floats2half2_rn(xr[6], 0.f);
                dst[4] = z2; dst[5] = z2; dst[6] = z2; dst[7] = z2;
            } else {
                #pragma unroll
                for (int i = 0; i < 8; i++) dst[i] = z2;
            }
        }
    } else {
        const int d = tid - 64;
        float a0 = __ldg(ego_b1 + d), a1 = 0.f;
        #pragma unroll 8
        for (int kp = 0; kp < 32; kp++) {
            float2 wv = __half22float2(__ldg(&dW1ep[kp * 64 + d]));
            float2 hv = *reinterpret_cast<const float2*>(&s.h0[2 * kp]);
            a0 += hv.x * wv.x;
            a1 += hv.y * wv.y;
        }
        s.sEgo[d] = fmaxf(a0 + a1, 0.f);
    }
    __syncthreads();

    // ---- PH4: layer0 HMMA (k16): Axh -> Ah0 (bias+relu) ----
    {
        uint2 bf0[2];
        bf0[0] = __ldg(&dF0[(g * 2) * 32 + lane]);
        bf0[1] = __ldg(&dF0[(g * 2 + 1) * 32 + lane]);
        for (int mtl = 0; mtl < ntm; mtl++) {
            u32 A[4];
            u32 ab = s2u(s.u1.Axh + (mtl * 16 + (lane & 15)) * AXS +
                         ((lane >> 4) << 3));
            ldsm4(A, ab);
            const int r0 = mtl * 16 + lr, r1 = r0 + 8;
            #pragma unroll
            for (int nt2 = 0; nt2 < 2; nt2++) {
                const int cA = (g * 2 + nt2) * 8 + col0;
                float c0 = __ldg(oth_b0 + cA), c1 = __ldg(oth_b0 + cA + 1);
                float c2 = c0, c3 = c1;
                mma16816(c0, c1, c2, c3, A, bf0[nt2].x, bf0[nt2].y);
                *reinterpret_cast<__half2*>(&s.Ah0[r0 * AHS + cA]) =
                    __floats2half2_rn(fmaxf(c0, 0.f), fmaxf(c1, 0.f));
                *reinterpret_cast<__half2*>(&s.Ah0[r1 * AHS + cA]) =
                    __floats2half2_rn(fmaxf(c2, 0.f), fmaxf(c3, 0.f));
            }
        }
    }
    __syncthreads();

    // ---- PH5: layer1 HMMA: Ah0 -> Ah1 (bias+relu+ego patch); then q ----
    {
        uint2 bf1[2][4];
        #pragma unroll
        for (int nt2 = 0; nt2 < 2; nt2++)
            #pragma unroll
            for (int kt = 0; kt < 4; kt++)
                bf1[nt2][kt] = __ldg(&dF1[(kt * 8 + g * 2 + nt2) * 32 + lane]);
        for (int mtl = 0; mtl < ntm; mtl++) {
            u32 A[4][4];
            u32 ab = s2u(s.Ah0 + (mtl * 16 + (lane & 15)) * AHS +
                         ((lane >> 4) << 3));
            #pragma unroll
            for (int kt = 0; kt < 4; kt++) ldsm4(A[kt], ab + kt * 32);
            const int r0 = mtl * 16 + lr, r1 = r0 + 8;
            #pragma unroll
            for (int nt2 = 0; nt2 < 2; nt2++) {
                const int cA = (g * 2 + nt2) * 8 + col0;
                float c0 = __ldg(oth_b1 + cA), c1 = __ldg(oth_b1 + cA + 1);
                float c2 = c0, c3 = c1;
                #pragma unroll
                for (int kt = 0; kt < 4; kt++)
                    mma16816(c0, c1, c2, c3, A[kt],
                             bf1[nt2][kt].x, bf1[nt2][kt].y);
                c0 = fmaxf(c0, 0.f); c1 = fmaxf(c1, 0.f);
                c2 = fmaxf(c2, 0.f); c3 = fmaxf(c3, 0.f);
                if (r0 == cEgo) { c0 = s.sEgo[cA]; c1 = s.sEgo[cA + 1]; }
                if (r1 == cEgo) { c2 = s.sEgo[cA]; c3 = s.sEgo[cA + 1]; }
                *reinterpret_cast<__half2*>(&s.u1.Ah1[r0 * AHS + cA]) =
                    __floats2half2_rn(c0, c1);
                *reinterpret_cast<__half2*>(&s.u1.Ah1[r1 * AHS + cA]) =
                    __floats2half2_rn(c2, c3);
            }
        }
    }
    if (tid < 64) {
        const int d = tid;
        float a0 = 0.f, a1 = 0.f;
        #pragma unroll 8
        for (int kp = 0; kp < 32; kp++) {
            float2 wv = __half22float2(__ldg(&dWqp[kp * 64 + d]));
            float2 ev = *reinterpret_cast<const float2*>(&s.sEgo[2 * kp]);
            a0 += ev.x * wv.x;
            a1 += ev.y * wv.y;
        }
        s.sQ[d] = a0 + a1;
    }
    __syncthreads();

    // ---- PH6-8: warp-local K -> softmax -> V -> P.V ----
    if (ntm == 2) attn_tail<2>(s, g, lane, nOth, cEgo, egoAct, uniformF);
    else          attn_tail<4>(s, g, lane, nOth, cEgo, egoAct, uniformF);
    __syncthreads();

    // ---- PH9: epilogue (out @ Wc + ego) * 0.5 ----
    if (tid < 64) {
        const int d = tid;
        float a0 = 0.f, a1 = 0.f;
        #pragma unroll 8
        for (int kp = 0; kp < 32; kp++) {
            float2 wv = __half22float2(__ldg(&dWcp[kp * 64 + d]));
            float2 ov = *reinterpret_cast<const float2*>(&s.sO[2 * kp]);
            a0 += ov.x * wv.x;
            a1 += ov.y * wv.y;
        }
        out[b * 64 + d] = ((a0 + a1) + s.sEgo[d]) * 0.5f;
    }
}

extern "C" void kernel_launch(void* const* d_in, const int* in_sizes, int n_in,
                              void* d_out, int out_size) {
    (void)in_sizes; (void)n_in; (void)out_size;
    const float* x      = (const float*)d_in[0];
    const float* ego_w0 = (const float*)d_in[1];
    const float* ego_b0 = (const float*)d_in[2];
    const float* ego_w1 = (const float*)d_in[3];
    const float* ego_b1 = (const float*)d_in[4];
    const float* oth_w0 = (const float*)d_in[5];
    const float* oth_b0 = (const float*)d_in[6];
    const float* oth_w1 = (const float*)d_in[7];
    const float* oth_b1 = (const float*)d_in[8];
    const float* Wk     = (const float*)d_in[9];
    const float* Wv     = (const float*)d_in[10];
    const float* Wq     = (const float*)d_in[11];
    const float* Wc     = (const float*)d_in[12];
    float* out = (float*)d_out;

    prep_weights<<<8, 256>>>(oth_w0, oth_w1, Wk, Wv, ego_w1, Wq, Wc);
    ego_attn_kernel<<<8192, NTHR>>>(x, ego_w0, ego_b0, ego_b1,
                                    oth_b0, oth_b1, out);
}

// round 16
// speedup vs baseline: 1.8681x; 1.0339x over previous
#include <cuda_runtime.h>
#include <cuda_fp16.h>

// EgoAttentionNetwork: B=8192, E=64, F_IN=7, D=64, H=4, HD=16
// Round-15 = Round-14 (61.5us; warp=head, 128-thr CTA, 8 CTAs/SM) +
//  - fused K+V attention tail (single ldsm pass; V held in regs across the
//    in-warp softmax) on the fast path (Mpad=32),
//  - q and epilogue mat-vecs split across all 128 threads (half k-range
//    each, smem combine),
//  - bias/q loads hoisted out of the mtl loops.

typedef unsigned int u32;

#define NTHR 128
#define FULLMASK 0xffffffffu
#define AXS 24     // Axh row stride in halves (48B: conflict-free ldsm)
#define AHS 72     // Ah0/Ah1 row stride in halves (144B)

__device__ uint2   dF0[256];     // oth_w0 B-fragments [nt(8)][lane], k padded to 16
__device__ uint2   dF1[1024];    // oth_w1 B-fragments [kt(4)][nt(8)][lane]
__device__ uint2   dFk[1024];    // Wk fragments
__device__ uint2   dFv[1024];    // Wv fragments
__device__ __half2 dW1ep[2048];  // ego_w1 k-pair packed
__device__ __half2 dWqp[2048];   // Wq k-pair packed
__device__ __half2 dWcp[2048];   // Wc k-pair packed

static __device__ __forceinline__ unsigned int f2h2(float a, float b) {
    __half2 h = __floats2half2_rn(a, b);
    return *reinterpret_cast<unsigned int*>(&h);
}
static __device__ __forceinline__ u32 s2u(const void* p) {
    return (u32)__cvta_generic_to_shared(p);
}
static __device__ __forceinline__ void ldsm4(u32* a, u32 addr) {
    asm volatile("ldmatrix.sync.aligned.m8n8.x4.shared.b16 {%0,%1,%2,%3}, [%4];"
                 : "=r"(a[0]), "=r"(a[1]), "=r"(a[2]), "=r"(a[3]) : "r"(addr));
}
static __device__ __forceinline__ void mma16816(
    float& c0, float& c1, float& c2, float& c3,
    const u32* a, u32 b0, u32 b1)
{
    asm volatile(
        "mma.sync.aligned.m16n8k16.row.col.f32.f16.f16.f32 "
        "{%0,%1,%2,%3}, {%4,%5,%6,%7}, {%8,%9}, {%0,%1,%2,%3};"
        : "+f"(c0), "+f"(c1), "+f"(c2), "+f"(c3)
        : "r"(a[0]), "r"(a[1]), "r"(a[2]), "r"(a[3]), "r"(b0), "r"(b1));
}

__device__ __forceinline__ u32 pkw(const float* W, int k, int n) {
    return f2h2(__ldg(W + k * 64 + n), __ldg(W + (k + 1) * 64 + n));
}
__device__ __forceinline__ u32 pkw7(const float* W, int k, int n) {
    float a = (k < 7) ? __ldg(W + k * 64 + n) : 0.f;
    float b = (k + 1 < 7) ? __ldg(W + (k + 1) * 64 + n) : 0.f;
    return f2h2(a, b);
}

__global__ void prep_weights(const float* __restrict__ oth_w0,
                             const float* __restrict__ oth_w1,
                             const float* __restrict__ Wk,
                             const float* __restrict__ Wv,
                             const float* __restrict__ ego_w1,
                             const float* __restrict__ Wq,
                             const float* __restrict__ Wc)
{
    const int i = blockIdx.x * 256 + threadIdx.x;   // 0..2047
    const int lane = i & 31;
    if (i < 256) {
        const int nt = i >> 5;
        const int n = nt * 8 + (lane >> 2);
        const int k = (lane & 3) * 2;
        dF0[i] = make_uint2(pkw7(oth_w0, k, n), pkw7(oth_w0, k + 8, n));
    }
    if (i < 1024) {
        const int nt = (i >> 5) & 7, kt = i >> 8;
        const int n = nt * 8 + (lane >> 2);
        const int k = kt * 16 + (lane & 3) * 2;
        dF1[i] = make_uint2(pkw(oth_w1, k, n), pkw(oth_w1, k + 8, n));
        dFk[i] = make_uint2(pkw(Wk, k, n),     pkw(Wk, k + 8, n));
        dFv[i] = make_uint2(pkw(Wv, k, n),     pkw(Wv, k + 8, n));
    }
    {
        const int kp = i >> 6, d = i & 63;
        const int k0 = 2 * kp * 64 + d, k1 = (2 * kp + 1) * 64 + d;
        dW1ep[i] = __floats2half2_rn(__ldg(ego_w1 + k0), __ldg(ego_w1 + k1));
        dWqp[i]  = __floats2half2_rn(__ldg(Wq + k0),     __ldg(Wq + k1));
        dWcp[i]  = __floats2half2_rn(__ldg(Wc + k0),     __ldg(Wc + k1));
    }
}

struct __align__(16) SmemT {
    union {
        __half Axh[64 * AXS];   // fp16 compacted x (live: PH3-PH4)
        __half Ah1[64 * AHS];   // input_all (live: PH5-end)
    } u1;
    __half Ah0[64 * AHS];       // hidden (layer0 out)
    float  sX[64 * 8];          // raw x; reused as epilogue partials
    float  h0[64];
    float  sEgo[64];
    float  sQa[64];             // q partial (kp 0-15)
    float  sQb[64];             // q partial (kp 16-31)
    float  sO[64];
    int    sIdx[64];
    int    nOth, uniformF, egoAct;
};

// Fast path (Mpad=32): fused K+V, one ldsm pass, V held across softmax.
__device__ __forceinline__ void attn_tail2(SmemT& s, int g, int lane,
                                           int nOth, int cEgo, int egoAct)
{
    const int col0 = (lane & 3) * 2;
    const int lr = lane >> 2;
    float q0[2], q1[2];
    #pragma unroll
    for (int nt2 = 0; nt2 < 2; nt2++) {
        const int cA = (g * 2 + nt2) * 8 + col0;
        q0[nt2] = s.sQa[cA]     + s.sQb[cA];
        q1[nt2] = s.sQa[cA + 1] + s.sQb[cA + 1];
    }
    float p[4];
    float vV[2][2][4];
    #pragma unroll
    for (int mtl = 0; mtl < 2; mtl++) {
        u32 A[4][4];
        u32 ab = s2u(s.u1.Ah1 + (mtl * 16 + (lane & 15)) * AHS +
                     ((lane >> 4) << 3));
        #pragma unroll
        for (int kt = 0; kt < 4; kt++) ldsm4(A[kt], ab + kt * 32);
        float p0 = 0.f, p1 = 0.f;
        #pragma unroll
        for (int nt2 = 0; nt2 < 2; nt2++) {
            float k0 = 0.f, k1 = 0.f, k2 = 0.f, k3 = 0.f;
            float v0 = 0.f, v1 = 0.f, v2 = 0.f, v3 = 0.f;
            #pragma unroll
            for (int kt = 0; kt < 4; kt++) {
                uint2 bk = __ldg(&dFk[(kt * 8 + g * 2 + nt2) * 32 + lane]);
                uint2 bv = __ldg(&dFv[(kt * 8 + g * 2 + nt2) * 32 + lane]);
                mma16816(k0, k1, k2, k3, A[kt], bk.x, bk.y);
                mma16816(v0, v1, v2, v3, A[kt], bv.x, bv.y);
            }
            p0 += k0 * q0[nt2] + k1 * q1[nt2];
            p1 += k2 * q0[nt2] + k3 * q1[nt2];
            vV[mtl][nt2][0] = v0; vV[mtl][nt2][1] = v1;
            vV[mtl][nt2][2] = v2; vV[mtl][nt2][3] = v3;
        }
        p0 += __shfl_xor_sync(FULLMASK, p0, 1);
        p1 += __shfl_xor_sync(FULLMASK, p1, 1);
        p0 += __shfl_xor_sync(FULLMASK, p0, 2);
        p1 += __shfl_xor_sync(FULLMASK, p1, 2);
        const int e0 = mtl * 16 + lr, e1 = e0 + 8;
        bool a0 = (e0 < nOth) || (e0 == cEgo && egoAct);
        bool a1 = (e1 < nOth) || (e1 == cEgo && egoAct);
        p[2 * mtl]     = a0 ? p0 * 0.25f : -1e30f;
        p[2 * mtl + 1] = a1 ? p1 * 0.25f : -1e30f;
    }
    // in-warp softmax (rows quad-replicated -> reduce over off 4,8,16)
    {
        float m = fmaxf(fmaxf(p[0], p[1]), fmaxf(p[2], p[3]));
        #pragma unroll
        for (int off = 4; off < 32; off <<= 1)
            m = fmaxf(m, __shfl_xor_sync(FULLMASK, m, off));
        float sum = 0.f;
        #pragma unroll
        for (int i = 0; i < 4; i++) { p[i] = __expf(p[i] - m); sum += p[i]; }
        #pragma unroll
        for (int off = 4; off < 32; off <<= 1)
            sum += __shfl_xor_sync(FULLMASK, sum, off);
        float inv = 1.0f / sum;
        #pragma unroll
        for (int i = 0; i < 4; i++) p[i] *= inv;
    }
    // apply P to held V and reduce
    float o00 = 0.f, o01 = 0.f, o10 = 0.f, o11 = 0.f;
    #pragma unroll
    for (int mtl = 0; mtl < 2; mtl++) {
        const float pr0 = p[2 * mtl], pr1 = p[2 * mtl + 1];
        o00 += pr0 * vV[mtl][0][0] + pr1 * vV[mtl][0][2];
        o01 += pr0 * vV[mtl][0][1] + pr1 * vV[mtl][0][3];
        o10 += pr0 * vV[mtl][1][0] + pr1 * vV[mtl][1][2];
        o11 += pr0 * vV[mtl][1][1] + pr1 * vV[mtl][1][3];
    }
    #pragma unroll
    for (int off = 4; off < 32; off <<= 1) {
        o00 += __shfl_xor_sync(FULLMASK, o00, off);
        o01 += __shfl_xor_sync(FULLMASK, o01, off);
        o10 += __shfl_xor_sync(FULLMASK, o10, off);
        o11 += __shfl_xor_sync(FULLMASK, o11, off);
    }
    if (lane < 4) {
        s.sO[(g * 2)     * 8 + lane * 2]     = o00;
        s.sO[(g * 2)     * 8 + lane * 2 + 1] = o01;
        s.sO[(g * 2 + 1) * 8 + lane * 2]     = o10;
        s.sO[(g * 2 + 1) * 8 + lane * 2 + 1] = o11;
    }
}

// Slow path (Mpad=64, incl. uniform batches): two-pass K then V.
__device__ __forceinline__ void attn_tail4(SmemT& s, int g, int lane,
                                           int nOth, int cEgo, int egoAct,
                                           int uniformF)
{
    const int col0 = (lane & 3) * 2;
    const int lr = lane >> 2;
    float q0[2], q1[2];
    #pragma unroll
    for (int nt2 = 0; nt2 < 2; nt2++) {
        const int cA = (g * 2 + nt2) * 8 + col0;
        q0[nt2] = s.sQa[cA]     + s.sQb[cA];
        q1[nt2] = s.sQa[cA + 1] + s.sQb[cA + 1];
    }
    float p[8];
    #pragma unroll
    for (int mtl = 0; mtl < 4; mtl++) {
        u32 A[4][4];
        u32 ab = s2u(s.u1.Ah1 + (mtl * 16 + (lane & 15)) * AHS +
                     ((lane >> 4) << 3));
        #pragma unroll
        for (int kt = 0; kt < 4; kt++) ldsm4(A[kt], ab + kt * 32);
        float p0 = 0.f, p1 = 0.f;
        #pragma unroll
        for (int nt2 = 0; nt2 < 2; nt2++) {
            float k0 = 0.f, k1 = 0.f, k2 = 0.f, k3 = 0.f;
            #pragma unroll
            for (int kt = 0; kt < 4; kt++) {
                uint2 bk = __ldg(&dFk[(kt * 8 + g * 2 + nt2) * 32 + lane]);
                mma16816(k0, k1, k2, k3, A[kt], bk.x, bk.y);
            }
            p0 += k0 * q0[nt2] + k1 * q1[nt2];
            p1 += k2 * q0[nt2] + k3 * q1[nt2];
        }
        p0 += __shfl_xor_sync(FULLMASK, p0, 1);
        p1 += __shfl_xor_sync(FULLMASK, p1, 1);
        p0 += __shfl_xor_sync(FULLMASK, p0, 2);
        p1 += __shfl_xor_sync(FULLMASK, p1, 2);
        const int e0 = mtl * 16 + lr, e1 = e0 + 8;
        bool a0 = (e0 < nOth) || (e0 == cEgo && egoAct);
        bool a1 = (e1 < nOth) || (e1 == cEgo && egoAct);
        p[2 * mtl]     = a0 ? p0 * 0.25f : -1e30f;
        p[2 * mtl + 1] = a1 ? p1 * 0.25f : -1e30f;
    }
    if (uniformF) {
        #pragma unroll
        for (int i = 0; i < 8; i++) p[i] = 1.0f / 64.0f;
    } else {
        float m = p[0];
        #pragma unroll
        for (int i = 1; i < 8; i++) m = fmaxf(m, p[i]);
        #pragma unroll
        for (int off = 4; off < 32; off <<= 1)
            m = fmaxf(m, __shfl_xor_sync(FULLMASK, m, off));
        float sum = 0.f;
        #pragma unroll
        for (int i = 0; i < 8; i++) { p[i] = __expf(p[i] - m); sum += p[i]; }
        #pragma unroll
        for (int off = 4; off < 32; off <<= 1)
            sum += __shfl_xor_sync(FULLMASK, sum, off);
        float inv = 1.0f / sum;
        #pragma unroll
        for (int i = 0; i < 8; i++) p[i] *= inv;
    }
    float o00 = 0.f, o01 = 0.f, o10 = 0.f, o11 = 0.f;
    #pragma unroll
    for (int mtl = 0; mtl < 4; mtl++) {
        u32 A[4][4];
        u32 ab = s2u(s.u1.Ah1 + (mtl * 16 + (lane & 15)) * AHS +
                     ((lane >> 4) << 3));
        #pragma unroll
        for (int kt = 0; kt < 4; kt++) ldsm4(A[kt], ab + kt * 32);
        const float pr0 = p[2 * mtl], pr1 = p[2 * mtl + 1];
        {
            float v0 = 0.f, v1 = 0.f, v2 = 0.f, v3 = 0.f;
            #pragma unroll
            for (int kt = 0; kt < 4; kt++) {
                uint2 bv = __ldg(&dFv[(kt * 8 + g * 2) * 32 + lane]);
                mma16816(v0, v1, v2, v3, A[kt], bv.x, bv.y);
            }
            o00 += pr0 * v0 + pr1 * v2;
            o01 += pr0 * v1 + pr1 * v3;
        }
        {
            float v0 = 0.f, v1 = 0.f, v2 = 0.f, v3 = 0.f;
            #pragma unroll
            for (int kt = 0; kt < 4; kt++) {
                uint2 bv = __ldg(&dFv[(kt * 8 + g * 2 + 1) * 32 + lane]);
                mma16816(v0, v1, v2, v3, A[kt], bv.x, bv.y);
            }
            o10 += pr0 * v0 + pr1 * v2;
            o11 += pr0 * v1 + pr1 * v3;
        }
    }
    #pragma unroll
    for (int off = 4; off < 32; off <<= 1) {
        o00 += __shfl_xor_sync(FULLMASK, o00, off);
        o01 += __shfl_xor_sync(FULLMASK, o01, off);
        o10 += __shfl_xor_sync(FULLMASK, o10, off);
        o11 += __shfl_xor_sync(FULLMASK, o11, off);
    }
    if (lane < 4) {
        s.sO[(g * 2)     * 8 + lane * 2]     = o00;
        s.sO[(g * 2)     * 8 + lane * 2 + 1] = o01;
        s.sO[(g * 2 + 1) * 8 + lane * 2]     = o10;
        s.sO[(g * 2 + 1) * 8 + lane * 2 + 1] = o11;
    }
}

__global__ void __launch_bounds__(NTHR, 8)
ego_attn_kernel(const float* __restrict__ x,
                const float* __restrict__ ego_w0, const float* __restrict__ ego_b0,
                const float* __restrict__ ego_b1,
                const float* __restrict__ oth_b0, const float* __restrict__ oth_b1,
                float* __restrict__ out)
{
    __shared__ SmemT s;
    const int tid = threadIdx.x;
    const int lane = tid & 31;
    const int g = tid >> 5;      // warp = head
    const long b = blockIdx.x;
    const float* xb = x + b * 448;
    const int col0 = (lane & 3) * 2;
    const int lr = lane >> 2;

    // ---- PH1: load x ----
    for (int idx = tid; idx < 448; idx += NTHR) {
        int e = idx / 7, f = idx - (idx / 7) * 7;
        s.sX[e * 8 + f] = __ldg(xb + idx);
    }
    __syncthreads();

    // ---- PH2: compaction (warp0) | ego layer0 (warp1) ----
    if (g == 0) {
        int egoA = (s.sX[0] >= 0.5f) ? 1 : 0;
        unsigned m1 = __ballot_sync(FULLMASK, (lane >= 1) && (s.sX[lane * 8] >= 0.5f));
        unsigned m2 = __ballot_sync(FULLMASK, s.sX[(lane + 32) * 8] >= 0.5f);
        int cnt = __popc(m1) + __popc(m2);
        unsigned lmask = (1u << lane) - 1u;
        if (cnt == 0 && !egoA) {
            s.sIdx[lane] = lane + 1;
            if (lane < 31) s.sIdx[lane + 32] = lane + 33;
            if (lane == 0) { s.nOth = 63; s.uniformF = 1; s.egoAct = egoA; }
        } else {
            if ((lane >= 1) && (m1 >> lane & 1u))
                s.sIdx[__popc(m1 & lmask)] = lane;
            if (m2 >> lane & 1u)
                s.sIdx[__popc(m1) + __popc(m2 & lmask)] = lane + 32;
            if (lane == 0) { s.nOth = cnt; s.uniformF = 0; s.egoAct = egoA; }
        }
    } else if (g == 1) {
        #pragma unroll
        for (int r = 0; r < 2; r++) {
            int d = lane + r * 32;
            float acc = __ldg(ego_b0 + d);
            #pragma unroll
            for (int f = 0; f < 7; f++)
                acc += s.sX[f] * __ldg(ego_w0 + f * 64 + d);
            s.h0[d] = fmaxf(acc, 0.f);
        }
    }
    __syncthreads();

    const int nOth = s.nOth;
    const int uniformF = s.uniformF;
    const int egoAct = s.egoAct;
    const int cEgo = nOth;
    const int nTot = nOth + 1;
    const int Mpad = (nTot <= 32) ? 32 : 64;
    const int ntm = Mpad >> 4;

    // ---- PH3: gather compacted x -> Axh fp16 (thr 0-63) | ego layer1 ----
    if (tid < 64) {
        const int row = tid;
        if (row < Mpad) {
            __half2* dst = reinterpret_cast<__half2*>(s.u1.Axh + row * AXS);
            const __half2 z2 = __floats2half2_rn(0.f, 0.f);
            if (row < nOth) {
                const float* xr = s.sX + s.sIdx[row] * 8;
                dst[0] = __floats2half2_rn(xr[0], xr[1]);
                dst[1] = __floats2half2_rn(xr[2], xr[3]);
                dst[2] = __floats2half2_rn(xr[4], xr[5]);
                dst[3] = __floats2half2_rn(xr[6], 0.f);
                dst[4] = z2; dst[5] = z2; dst[6] = z2; dst[7] = z2;
            } else {
                #pragma unroll
                for (int i = 0; i < 8; i++) dst[i] = z2;
            }
        }
    } else {
        const int d = tid - 64;
        float a0 = __ldg(ego_b1 + d), a1 = 0.f;
        #pragma unroll 8
        for (int kp = 0; kp < 32; kp++) {
            float2 wv = __half22float2(__ldg(&dW1ep[kp * 64 + d]));
            float2 hv = *reinterpret_cast<const float2*>(&s.h0[2 * kp]);
            a0 += hv.x * wv.x;
            a1 += hv.y * wv.y;
        }
        s.sEgo[d] = fmaxf(a0 + a1, 0.f);
    }
    __syncthreads();

    // ---- PH4: layer0 HMMA (k16): Axh -> Ah0 (bias+relu) ----
    {
        uint2 bf0[2];
        float bb[2][2];
        #pragma unroll
        for (int nt2 = 0; nt2 < 2; nt2++) {
            bf0[nt2] = __ldg(&dF0[(g * 2 + nt2) * 32 + lane]);
            const int cA = (g * 2 + nt2) * 8 + col0;
            bb[nt2][0] = __ldg(oth_b0 + cA);
            bb[nt2][1] = __ldg(oth_b0 + cA + 1);
        }
        for (int mtl = 0; mtl < ntm; mtl++) {
            u32 A[4];
            u32 ab = s2u(s.u1.Axh + (mtl * 16 + (lane & 15)) * AXS +
                         ((lane >> 4) << 3));
            ldsm4(A, ab);
            const int r0 = mtl * 16 + lr, r1 = r0 + 8;
            #pragma unroll
            for (int nt2 = 0; nt2 < 2; nt2++) {
                const int cA = (g * 2 + nt2) * 8 + col0;
                float c0 = bb[nt2][0], c1 = bb[nt2][1];
                float c2 = c0, c3 = c1;
                mma16816(c0, c1, c2, c3, A, bf0[nt2].x, bf0[nt2].y);
                *reinterpret_cast<__half2*>(&s.Ah0[r0 * AHS + cA]) =
                    __floats2half2_rn(fmaxf(c0, 0.f), fmaxf(c1, 0.f));
                *reinterpret_cast<__half2*>(&s.Ah0[r1 * AHS + cA]) =
                    __floats2half2_rn(fmaxf(c2, 0.f), fmaxf(c3, 0.f));
            }
        }
    }
    __syncthreads();

    // ---- PH5: layer1 HMMA: Ah0 -> Ah1 (bias+relu+ego patch); then q ----
    {
        uint2 bf1[2][4];
        float bb[2][2];
        #pragma unroll
        for (int nt2 = 0; nt2 < 2; nt2++) {
            #pragma unroll
            for (int kt = 0; kt < 4; kt++)
                bf1[nt2][kt] = __ldg(&dF1[(kt * 8 + g * 2 + nt2) * 32 + lane]);
            const int cA = (g * 2 + nt2) * 8 + col0;
            bb[nt2][0] = __ldg(oth_b1 + cA);
            bb[nt2][1] = __ldg(oth_b1 + cA + 1);
        }
        for (int mtl = 0; mtl < ntm; mtl++) {
            u32 A[4][4];
            u32 ab = s2u(s.Ah0 + (mtl * 16 + (lane & 15)) * AHS +
                         ((lane >> 4) << 3));
            #pragma unroll
            for (int kt = 0; kt < 4; kt++) ldsm4(A[kt], ab + kt * 32);
            const int r0 = mtl * 16 + lr, r1 = r0 + 8;
            #pragma unroll
            for (int nt2 = 0; nt2 < 2; nt2++) {
                const int cA = (g * 2 + nt2) * 8 + col0;
                float c0 = bb[nt2][0], c1 = bb[nt2][1];
                float c2 = c0, c3 = c1;
                #pragma unroll
                for (int kt = 0; kt < 4; kt++)
                    mma16816(c0, c1, c2, c3, A[kt],
                             bf1[nt2][kt].x, bf1[nt2][kt].y);
                c0 = fmaxf(c0, 0.f); c1 = fmaxf(c1, 0.f);
                c2 = fmaxf(c2, 0.f); c3 = fmaxf(c3, 0.f);
                if (r0 == cEgo) { c0 = s.sEgo[cA]; c1 = s.sEgo[cA + 1]; }
                if (r1 == cEgo) { c2 = s.sEgo[cA]; c3 = s.sEgo[cA + 1]; }
                *reinterpret_cast<__half2*>(&s.u1.Ah1[r0 * AHS + cA]) =
                    __floats2half2_rn(c0, c1);
                *reinterpret_cast<__half2*>(&s.u1.Ah1[r1 * AHS + cA]) =
                    __floats2half2_rn(c2, c3);
            }
        }
    }
    // q split across all 128 threads: half k-range each
    {
        const int half = tid >> 6, d = tid & 63;
        const int kp0 = half * 16;
        float a0 = 0.f, a1 = 0.f;
        #pragma unroll 8
        for (int kp = kp0; kp < kp0 + 16; kp++) {
            float2 wv = __half22float2(__ldg(&dWqp[kp * 64 + d]));
            float2 ev = *reinterpret_cast<const float2*>(&s.sEgo[2 * kp]);
            a0 += ev.x * wv.x;
            a1 += ev.y * wv.y;
        }
        (half ? s.sQb : s.sQa)[d] = a0 + a1;
    }
    __syncthreads();

    // ---- PH6-8: warp-local K -> softmax -> V -> P.V ----
    if (ntm == 2) attn_tail2(s, g, lane, nOth, cEgo, egoAct);
    else          attn_tail4(s, g, lane, nOth, cEgo, egoAct, uniformF);
    __syncthreads();

    // ---- PH9: epilogue (out @ Wc + ego) * 0.5, split across 128 thr ----
    {
        float* sPar = s.sX;   // raw x dead; reuse as partials
        const int half = tid >> 6, d = tid & 63;
        const int kp0 = half * 16;
        float a0 = 0.f, a1 = 0.f;
        #pragma unroll 8
        for (int kp = kp0; kp < kp0 + 16; kp++) {
            float2 wv = __half22float2(__ldg(&dWcp[kp * 64 + d]));
            float2 ov = *reinterpret_cast<const float2*>(&s.sO[2 * kp]);
            a0 += ov.x * wv.x;
            a1 += ov.y * wv.y;
        }
        sPar[tid] = a0 + a1;
        __syncthreads();
        if (tid < 64)
            out[b * 64 + tid] = ((sPar[tid] + sPar[64 + tid]) + s.sEgo[tid]) * 0.5f;
    }
}

extern "C" void kernel_launch(void* const* d_in, const int* in_sizes, int n_in,
                              void* d_out, int out_size) {
    (void)in_sizes; (void)n_in; (void)out_size;
    const float* x      = (const float*)d_in[0];
    const float* ego_w0 = (const float*)d_in[1];
    const float* ego_b0 = (const float*)d_in[2];
    const float* ego_w1 = (const float*)d_in[3];
    const float* ego_b1 = (const float*)d_in[4];
    const float* oth_w0 = (const float*)d_in[5];
    const float* oth_b0 = (const float*)d_in[6];
    const float* oth_w1 = (const float*)d_in[7];
    const float* oth_b1 = (const float*)d_in[8];
    const float* Wk     = (const float*)d_in[9];
    const float* Wv     = (const float*)d_in[10];
    const float* Wq     = (const float*)d_in[11];
    const float* Wc     = (const float*)d_in[12];
    float* out = (float*)d_out;

    prep_weights<<<8, 256>>>(oth_w0, oth_w1, Wk, Wv, ego_w1, Wq, Wc);
    ego_attn_kernel<<<8192, NTHR>>>(x, ego_w0, ego_b0, ego_b1,
                                    oth_b0, oth_b1, out);
}

// round 17
// speedup vs baseline: 1.9914x; 1.0660x over previous
#include <cuda_runtime.h>
#include <cuda_fp16.h>

// EgoAttentionNetwork: B=8192, E=64, F_IN=7, D=64, H=4, HD=16
// Round-16 = Round-15 (59.5us) + alu/address-math diet:
//  - PH1 x load as float4 (no div/mod-by-7), sX raw contiguous (stride 7
//    rows are conflict-free mod 32)
//  - ldsm row-offset math hoisted once per kernel
//  - K-fragment loads hoisted above the fused-tail MMA loop

typedef unsigned int u32;

#define NTHR 128
#define FULLMASK 0xffffffffu
#define AXS 24     // Axh row stride in halves (48B: conflict-free ldsm)
#define AHS 72     // Ah0/Ah1 row stride in halves (144B)

__device__ uint2   dF0[256];     // oth_w0 B-fragments [nt(8)][lane], k padded to 16
__device__ uint2   dF1[1024];    // oth_w1 B-fragments [kt(4)][nt(8)][lane]
__device__ uint2   dFk[1024];    // Wk fragments
__device__ uint2   dFv[1024];    // Wv fragments
__device__ __half2 dW1ep[2048];  // ego_w1 k-pair packed
__device__ __half2 dWqp[2048];   // Wq k-pair packed
__device__ __half2 dWcp[2048];   // Wc k-pair packed

static __device__ __forceinline__ unsigned int f2h2(float a, float b) {
    __half2 h = __floats2half2_rn(a, b);
    return *reinterpret_cast<unsigned int*>(&h);
}
static __device__ __forceinline__ u32 s2u(const void* p) {
    return (u32)__cvta_generic_to_shared(p);
}
static __device__ __forceinline__ void ldsm4(u32* a, u32 addr) {
    asm volatile("ldmatrix.sync.aligned.m8n8.x4.shared.b16 {%0,%1,%2,%3}, [%4];"
                 : "=r"(a[0]), "=r"(a[1]), "=r"(a[2]), "=r"(a[3]) : "r"(addr));
}
static __device__ __forceinline__ void mma16816(
    float& c0, float& c1, float& c2, float& c3,
    const u32* a, u32 b0, u32 b1)
{
    asm volatile(
        "mma.sync.aligned.m16n8k16.row.col.f32.f16.f16.f32 "
        "{%0,%1,%2,%3}, {%4,%5,%6,%7}, {%8,%9}, {%0,%1,%2,%3};"
        : "+f"(c0), "+f"(c1), "+f"(c2), "+f"(c3)
        : "r"(a[0]), "r"(a[1]), "r"(a[2]), "r"(a[3]), "r"(b0), "r"(b1));
}

__device__ __forceinline__ u32 pkw(const float* W, int k, int n) {
    return f2h2(__ldg(W + k * 64 + n), __ldg(W + (k + 1) * 64 + n));
}
__device__ __forceinline__ u32 pkw7(const float* W, int k, int n) {
    float a = (k < 7) ? __ldg(W + k * 64 + n) : 0.f;
    float b = (k + 1 < 7) ? __ldg(W + (k + 1) * 64 + n) : 0.f;
    return f2h2(a, b);
}

__global__ void prep_weights(const float* __restrict__ oth_w0,
                             const float* __restrict__ oth_w1,
                             const float* __restrict__ Wk,
                             const float* __restrict__ Wv,
                             const float* __restrict__ ego_w1,
                             const float* __restrict__ Wq,
                             const float* __restrict__ Wc)
{
    const int i = blockIdx.x * 256 + threadIdx.x;   // 0..2047
    const int lane = i & 31;
    if (i < 256) {
        const int nt = i >> 5;
        const int n = nt * 8 + (lane >> 2);
        const int k = (lane & 3) * 2;
        dF0[i] = make_uint2(pkw7(oth_w0, k, n), pkw7(oth_w0, k + 8, n));
    }
    if (i < 1024) {
        const int nt = (i >> 5) & 7, kt = i >> 8;
        const int n = nt * 8 + (lane >> 2);
        const int k = kt * 16 + (lane & 3) * 2;
        dF1[i] = make_uint2(pkw(oth_w1, k, n), pkw(oth_w1, k + 8, n));
        dFk[i] = make_uint2(pkw(Wk, k, n),     pkw(Wk, k + 8, n));
        dFv[i] = make_uint2(pkw(Wv, k, n),     pkw(Wv, k + 8, n));
    }
    {
        const int kp = i >> 6, d = i & 63;
        const int k0 = 2 * kp * 64 + d, k1 = (2 * kp + 1) * 64 + d;
        dW1ep[i] = __floats2half2_rn(__ldg(ego_w1 + k0), __ldg(ego_w1 + k1));
        dWqp[i]  = __floats2half2_rn(__ldg(Wq + k0),     __ldg(Wq + k1));
        dWcp[i]  = __floats2half2_rn(__ldg(Wc + k0),     __ldg(Wc + k1));
    }
}

struct __align__(16) SmemT {
    union {
        __half Axh[64 * AXS];   // fp16 compacted x (live: PH3-PH4)
        __half Ah1[64 * AHS];   // input_all (live: PH5-end)
    } u1;
    __half Ah0[64 * AHS];       // hidden (layer0 out)
    float  sX[448];             // raw x, contiguous [e*7+f]
    float  sPar[128];           // epilogue partials
    float  h0[64];
    float  sEgo[64];
    float  sQa[64];             // q partial (kp 0-15)
    float  sQb[64];             // q partial (kp 16-31)
    float  sO[64];
    int    sIdx[64];
    int    nOth, uniformF, egoAct;
};

// Fast path (Mpad=32): fused K+V, one ldsm pass, V held across softmax.
__device__ __forceinline__ void attn_tail2(SmemT& s, int g, int lane,
                                           u32 rowH, int nOth, int cEgo,
                                           int egoAct)
{
    const int col0 = (lane & 3) * 2;
    const int lr = lane >> 2;
    float q0[2], q1[2];
    #pragma unroll
    for (int nt2 = 0; nt2 < 2; nt2++) {
        const int cA = (g * 2 + nt2) * 8 + col0;
        q0[nt2] = s.sQa[cA]     + s.sQb[cA];
        q1[nt2] = s.sQa[cA + 1] + s.sQb[cA + 1];
    }
    uint2 bk[2][4];
    #pragma unroll
    for (int nt2 = 0; nt2 < 2; nt2++)
        #pragma unroll
        for (int kt = 0; kt < 4; kt++)
            bk[nt2][kt] = __ldg(&dFk[(kt * 8 + g * 2 + nt2) * 32 + lane]);
    float p[4];
    float vV[2][2][4];
    const u32 abase = s2u(s.u1.Ah1) + rowH;
    #pragma unroll
    for (int mtl = 0; mtl < 2; mtl++) {
        u32 A[4][4];
        const u32 ab = abase + mtl * (16 * AHS * 2);
        #pragma unroll
        for (int kt = 0; kt < 4; kt++) ldsm4(A[kt], ab + kt * 32);
        float p0 = 0.f, p1 = 0.f;
        #pragma unroll
        for (int nt2 = 0; nt2 < 2; nt2++) {
            float k0 = 0.f, k1 = 0.f, k2 = 0.f, k3 = 0.f;
            float v0 = 0.f, v1 = 0.f, v2 = 0.f, v3 = 0.f;
            #pragma unroll
            for (int kt = 0; kt < 4; kt++) {
                uint2 bv = __ldg(&dFv[(kt * 8 + g * 2 + nt2) * 32 + lane]);
                mma16816(k0, k1, k2, k3, A[kt], bk[nt2][kt].x, bk[nt2][kt].y);
                mma16816(v0, v1, v2, v3, A[kt], bv.x, bv.y);
            }
            p0 += k0 * q0[nt2] + k1 * q1[nt2];
            p1 += k2 * q0[nt2] + k3 * q1[nt2];
            vV[mtl][nt2][0] = v0; vV[mtl][nt2][1] = v1;
            vV[mtl][nt2][2] = v2; vV[mtl][nt2][3] = v3;
        }
        p0 += __shfl_xor_sync(FULLMASK, p0, 1);
        p1 += __shfl_xor_sync(FULLMASK, p1, 1);
        p0 += __shfl_xor_sync(FULLMASK, p0, 2);
        p1 += __shfl_xor_sync(FULLMASK, p1, 2);
        const int e0 = mtl * 16 + lr, e1 = e0 + 8;
        bool a0 = (e0 < nOth) || (e0 == cEgo && egoAct);
        bool a1 = (e1 < nOth) || (e1 == cEgo && egoAct);
        p[2 * mtl]     = a0 ? p0 * 0.25f : -1e30f;
        p[2 * mtl + 1] = a1 ? p1 * 0.25f : -1e30f;
    }
    // in-warp softmax (rows quad-replicated -> reduce over off 4,8,16)
    {
        float m = fmaxf(fmaxf(p[0], p[1]), fmaxf(p[2], p[3]));
        #pragma unroll
        for (int off = 4; off < 32; off <<= 1)
            m = fmaxf(m, __shfl_xor_sync(FULLMASK, m, off));
        float sum = 0.f;
        #pragma unroll
        for (int i = 0; i < 4; i++) { p[i] = __expf(p[i] - m); sum += p[i]; }
        #pragma unroll
        for (int off = 4; off < 32; off <<= 1)
            sum += __shfl_xor_sync(FULLMASK, sum, off);
        float inv = 1.0f / sum;
        #pragma unroll
        for (int i = 0; i < 4; i++) p[i] *= inv;
    }
    float o00 = 0.f, o01 = 0.f, o10 = 0.f, o11 = 0.f;
    #pragma unroll
    for (int mtl = 0; mtl < 2; mtl++) {
        const float pr0 = p[2 * mtl], pr1 = p[2 * mtl + 1];
        o00 += pr0 * vV[mtl][0][0] + pr1 * vV[mtl][0][2];
        o01 += pr0 * vV[mtl][0][1] + pr1 * vV[mtl][0][3];
        o10 += pr0 * vV[mtl][1][0] + pr1 * vV[mtl][1][2];
        o11 += pr0 * vV[mtl][1][1] + pr1 * vV[mtl][1][3];
    }
    #pragma unroll
    for (int off = 4; off < 32; off <<= 1) {
        o00 += __shfl_xor_sync(FULLMASK, o00, off);
        o01 += __shfl_xor_sync(FULLMASK, o01, off);
        o10 += __shfl_xor_sync(FULLMASK, o10, off);
        o11 += __shfl_xor_sync(FULLMASK, o11, off);
    }
    if (lane < 4) {
        s.sO[(g * 2)     * 8 + lane * 2]     = o00;
        s.sO[(g * 2)     * 8 + lane * 2 + 1] = o01;
        s.sO[(g * 2 + 1) * 8 + lane * 2]     = o10;
        s.sO[(g * 2 + 1) * 8 + lane * 2 + 1] = o11;
    }
}

// Slow path (Mpad=64, incl. uniform batches): two-pass K then V.
__device__ __forceinline__ void attn_tail4(SmemT& s, int g, int lane,
                                           u32 rowH, int nOth, int cEgo,
                                           int egoAct, int uniformF)
{
    const int col0 = (lane & 3) * 2;
    const int lr = lane >> 2;
    float q0[2], q1[2];
    #pragma unroll
    for (int nt2 = 0; nt2 < 2; nt2++) {
        const int cA = (g * 2 + nt2) * 8 + col0;
        q0[nt2] = s.sQa[cA]     + s.sQb[cA];
        q1[nt2] = s.sQa[cA + 1] + s.sQb[cA + 1];
    }
    const u32 abase = s2u(s.u1.Ah1) + rowH;
    float p[8];
    #pragma unroll
    for (int mtl = 0; mtl < 4; mtl++) {
        u32 A[4][4];
        const u32 ab = abase + mtl * (16 * AHS * 2);
        #pragma unroll
        for (int kt = 0; kt < 4; kt++) ldsm4(A[kt], ab + kt * 32);
        float p0 = 0.f, p1 = 0.f;
        #pragma unroll
        for (int nt2 = 0; nt2 < 2; nt2++) {
            float k0 = 0.f, k1 = 0.f, k2 = 0.f, k3 = 0.f;
            #pragma unroll
            for (int kt = 0; kt < 4; kt++) {
                uint2 bk = __ldg(&dFk[(kt * 8 + g * 2 + nt2) * 32 + lane]);
                mma16816(k0, k1, k2, k3, A[kt], bk.x, bk.y);
            }
            p0 += k0 * q0[nt2] + k1 * q1[nt2];
            p1 += k2 * q0[nt2] + k3 * q1[nt2];
        }
        p0 += __shfl_xor_sync(FULLMASK, p0, 1);
        p1 += __shfl_xor_sync(FULLMASK, p1, 1);
        p0 += __shfl_xor_sync(FULLMASK, p0, 2);
        p1 += __shfl_xor_sync(FULLMASK, p1, 2);
        const int e0 = mtl * 16 + lr, e1 = e0 + 8;
        bool a0 = (e0 < nOth) || (e0 == cEgo && egoAct);
        bool a1 = (e1 < nOth) || (e1 == cEgo && egoAct);
        p[2 * mtl]     = a0 ? p0 * 0.25f : -1e30f;
        p[2 * mtl + 1] = a1 ? p1 * 0.25f : -1e30f;
    }
    if (uniformF) {
        #pragma unroll
        for (int i = 0; i < 8; i++) p[i] = 1.0f / 64.0f;
    } else {
        float m = p[0];
        #pragma unroll
        for (int i = 1; i < 8; i++) m = fmaxf(m, p[i]);
        #pragma unroll
        for (int off = 4; off < 32; off <<= 1)
            m = fmaxf(m, __shfl_xor_sync(FULLMASK, m, off));
        float sum = 0.f;
        #pragma unroll
        for (int i = 0; i < 8; i++) { p[i] = __expf(p[i] - m); sum += p[i]; }
        #pragma unroll
        for (int off = 4; off < 32; off <<= 1)
            sum += __shfl_xor_sync(FULLMASK, sum, off);
        float inv = 1.0f / sum;
        #pragma unroll
        for (int i = 0; i < 8; i++) p[i] *= inv;
    }
    float o00 = 0.f, o01 = 0.f, o10 = 0.f, o11 = 0.f;
    #pragma unroll
    for (int mtl = 0; mtl < 4; mtl++) {
        u32 A[4][4];
        const u32 ab = abase + mtl * (16 * AHS * 2);
        #pragma unroll
        for (int kt = 0; kt < 4; kt++) ldsm4(A[kt], ab + kt * 32);
        const float pr0 = p[2 * mtl], pr1 = p[2 * mtl + 1];
        {
            float v0 = 0.f, v1 = 0.f, v2 = 0.f, v3 = 0.f;
            #pragma unroll
            for (int kt = 0; kt < 4; kt++) {
                uint2 bv = __ldg(&dFv[(kt * 8 + g * 2) * 32 + lane]);
                mma16816(v0, v1, v2, v3, A[kt], bv.x, bv.y);
            }
            o00 += pr0 * v0 + pr1 * v2;
            o01 += pr0 * v1 + pr1 * v3;
        }
        {
            float v0 = 0.f, v1 = 0.f, v2 = 0.f, v3 = 0.f;
            #pragma unroll
            for (int kt = 0; kt < 4; kt++) {
                uint2 bv = __ldg(&dFv[(kt * 8 + g * 2 + 1) * 32 + lane]);
                mma16816(v0, v1, v2, v3, A[kt], bv.x, bv.y);
            }
            o10 += pr0 * v0 + pr1 * v2;
            o11 += pr0 * v1 + pr1 * v3;
        }
    }
    #pragma unroll
    for (int off = 4; off < 32; off <<= 1) {
        o00 += __shfl_xor_sync(FULLMASK, o00, off);
        o01 += __shfl_xor_sync(FULLMASK, o01, off);
        o10 += __shfl_xor_sync(FULLMASK, o10, off);
        o11 += __shfl_xor_sync(FULLMASK, o11, off);
    }
    if (lane < 4) {
        s.sO[(g * 2)     * 8 + lane * 2]     = o00;
        s.sO[(g * 2)     * 8 + lane * 2 + 1] = o01;
        s.sO[(g * 2 + 1) * 8 + lane * 2]     = o10;
        s.sO[(g * 2 + 1) * 8 + lane * 2 + 1] = o11;
    }
}

__global__ void __launch_bounds__(NTHR, 8)
ego_attn_kernel(const float* __restrict__ x,
                const float* __restrict__ ego_w0, const float* __restrict__ ego_b0,
                const float* __restrict__ ego_b1,
                const float* __restrict__ oth_b0, const float* __restrict__ oth_b1,
                float* __restrict__ out)
{
    __shared__ SmemT s;
    const int tid = threadIdx.x;
    const int lane = tid & 31;
    const int g = tid >> 5;      // warp = head
    const long b = blockIdx.x;
    const float* xb = x + b * 448;
    const int col0 = (lane & 3) * 2;
    const int lr = lane >> 2;
    // hoisted ldsm row offsets (bytes)
    const u32 rowH = ((lane & 15) * AHS + ((lane >> 4) << 3)) * 2;
    const u32 rowX = ((lane & 15) * AXS + ((lane >> 4) << 3)) * 2;

    // ---- PH1: load x (float4, contiguous) ----
    if (tid < 112)
        reinterpret_cast<float4*>(s.sX)[tid] =
            __ldg(reinterpret_cast<const float4*>(xb) + tid);
    __syncthreads();

    // ---- PH2: compaction (warp0) | ego layer0 (warp1) ----
    if (g == 0) {
        int egoA = (s.sX[0] >= 0.5f) ? 1 : 0;
        unsigned m1 = __ballot_sync(FULLMASK, (lane >= 1) && (s.sX[lane * 7] >= 0.5f));
        unsigned m2 = __ballot_sync(FULLMASK, s.sX[(lane + 32) * 7] >= 0.5f);
        int cnt = __popc(m1) + __popc(m2);
        unsigned lmask = (1u << lane) - 1u;
        if (cnt == 0 && !egoA) {
            s.sIdx[lane] = lane + 1;
            if (lane < 31) s.sIdx[lane + 32] = lane + 33;
            if (lane == 0) { s.nOth = 63; s.uniformF = 1; s.egoAct = egoA; }
        } else {
            if ((lane >= 1) && (m1 >> lane & 1u))
                s.sIdx[__popc(m1 & lmask)] = lane;
            if (m2 >> lane & 1u)
                s.sIdx[__popc(m1) + __popc(m2 & lmask)] = lane + 32;
            if (lane == 0) { s.nOth = cnt; s.uniformF = 0; s.egoAct = egoA; }
        }
    } else if (g == 1) {
        #pragma unroll
        for (int r = 0; r < 2; r++) {
            int d = lane + r * 32;
            float acc = __ldg(ego_b0 + d);
            #pragma unroll
            for (int f = 0; f < 7; f++)
                acc += s.sX[f] * __ldg(ego_w0 + f * 64 + d);
            s.h0[d] = fmaxf(acc, 0.f);
        }
    }
    __syncthreads();

    const int nOth = s.nOth;
    const int uniformF = s.uniformF;
    const int egoAct = s.egoAct;
    const int cEgo = nOth;
    const int nTot = nOth + 1;
    const int Mpad = (nTot <= 32) ? 32 : 64;
    const int ntm = Mpad >> 4;

    // ---- PH3: gather compacted x -> Axh fp16 (thr 0-63) | ego layer1 ----
    if (tid < 64) {
        const int row = tid;
        if (row < Mpad) {
            __half2* dst = reinterpret_cast<__half2*>(s.u1.Axh + row * AXS);
            const __half2 z2 = __floats2half2_rn(0.f, 0.f);
            if (row < nOth) {
                const float* xr = s.sX + s.sIdx[row] * 7;
                dst[0] = __floats2half2_rn(xr[0], xr[1]);
                dst[1] = __floats2half2_rn(xr[2], xr[3]);
                dst[2] = __floats2half2_rn(xr[4], xr[5]);
                dst[3] = __floats2half2_rn(xr[6], 0.f);
                dst[4] = z2; dst[5] = z2; dst[6] = z2; dst[7] = z2;
            } else {
                #pragma unroll
                for (int i = 0; i < 8; i++) dst[i] = z2;
            }
        }
    } else {
        const int d = tid - 64;
        float a0 = __ldg(ego_b1 + d), a1 = 0.f;
        #pragma unroll 8
        for (int kp = 0; kp < 32; kp++) {
            float2 wv = __half22float2(__ldg(&dW1ep[kp * 64 + d]));
            float2 hv = *reinterpret_cast<const float2*>(&s.h0[2 * kp]);
            a0 += hv.x * wv.x;
            a1 += hv.y * wv.y;
        }
        s.sEgo[d] = fmaxf(a0 + a1, 0.f);
    }
    __syncthreads();

    // ---- PH4: layer0 HMMA (k16): Axh -> Ah0 (bias+relu) ----
    {
        uint2 bf0[2];
        float bb[2][2];
        #pragma unroll
        for (int nt2 = 0; nt2 < 2; nt2++) {
            bf0[nt2] = __ldg(&dF0[(g * 2 + nt2) * 32 + lane]);
            const int cA = (g * 2 + nt2) * 8 + col0;
            bb[nt2][0] = __ldg(oth_b0 + cA);
            bb[nt2][1] = __ldg(oth_b0 + cA + 1);
        }
        const u32 abase = s2u(s.u1.Axh) + rowX;
        for (int mtl = 0; mtl < ntm; mtl++) {
            u32 A[4];
            ldsm4(A, abase + mtl * (16 * AXS * 2));
            const int r0 = mtl * 16 + lr, r1 = r0 + 8;
            #pragma unroll
            for (int nt2 = 0; nt2 < 2; nt2++) {
                const int cA = (g * 2 + nt2) * 8 + col0;
                float c0 = bb[nt2][0], c1 = bb[nt2][1];
                float c2 = c0, c3 = c1;
                mma16816(c0, c1, c2, c3, A, bf0[nt2].x, bf0[nt2].y);
                *reinterpret_cast<__half2*>(&s.Ah0[r0 * AHS + cA]) =
                    __floats2half2_rn(fmaxf(c0, 0.f), fmaxf(c1, 0.f));
                *reinterpret_cast<__half2*>(&s.Ah0[r1 * AHS + cA]) =
                    __floats2half2_rn(fmaxf(c2, 0.f), fmaxf(c3, 0.f));
            }
        }
    }
    __syncthreads();

    // ---- PH5: layer1 HMMA: Ah0 -> Ah1 (bias+relu+ego patch); then q ----
    {
        uint2 bf1[2][4];
        float bb[2][2];
        #pragma unroll
        for (int nt2 = 0; nt2 < 2; nt2++) {
            #pragma unroll
            for (int kt = 0; kt < 4; kt++)
                bf1[nt2][kt] = __ldg(&dF1[(kt * 8 + g * 2 + nt2) * 32 + lane]);
            const int cA = (g * 2 + nt2) * 8 + col0;
            bb[nt2][0] = __ldg(oth_b1 + cA);
            bb[nt2][1] = __ldg(oth_b1 + cA + 1);
        }
        const u32 abase = s2u(s.Ah0) + rowH;
        for (int mtl = 0; mtl < ntm; mtl++) {
            u32 A[4][4];
            const u32 ab = abase + mtl * (16 * AHS * 2);
            #pragma unroll
            for (int kt = 0; kt < 4; kt++) ldsm4(A[kt], ab + kt * 32);
            const int r0 = mtl * 16 + lr, r1 = r0 + 8;
            #pragma unroll
            for (int nt2 = 0; nt2 < 2; nt2++) {
                const int cA = (g * 2 + nt2) * 8 + col0;
                float c0 = bb[nt2][0], c1 = bb[nt2][1];
                float c2 = c0, c3 = c1;
                #pragma unroll
                for (int kt = 0; kt < 4; kt++)
                    mma16816(c0, c1, c2, c3, A[kt],
                             bf1[nt2][kt].x, bf1[nt2][kt].y);
                c0 = fmaxf(c0, 0.f); c1 = fmaxf(c1, 0.f);
                c2 = fmaxf(c2, 0.f); c3 = fmaxf(c3, 0.f);
                if (r0 == cEgo) { c0 = s.sEgo[cA]; c1 = s.sEgo[cA + 1]; }
                if (r1 == cEgo) { c2 = s.sEgo[cA]; c3 = s.sEgo[cA + 1]; }
                *reinterpret_cast<__half2*>(&s.u1.Ah1[r0 * AHS + cA]) =
                    __floats2half2_rn(c0, c1);
                *reinterpret_cast<__half2*>(&s.u1.Ah1[r1 * AHS + cA]) =
                    __floats2half2_rn(c2, c3);
            }
        }
    }
    // q split across all 128 threads: half k-range each
    {
        const int half = tid >> 6, d = tid & 63;
        const int kp0 = half * 16;
        float a0 = 0.f, a1 = 0.f;
        #pragma unroll 8
        for (int kp = kp0; kp < kp0 + 16; kp++) {
            float2 wv = __half22float2(__ldg(&dWqp[kp * 64 + d]));
            float2 ev = *reinterpret_cast<const float2*>(&s.sEgo[2 * kp]);
            a0 += ev.x * wv.x;
            a1 += ev.y * wv.y;
        }
        (half ? s.sQb : s.sQa)[d] = a0 + a1;
    }
    __syncthreads();

    // ---- PH6-8: warp-local K -> softmax -> V -> P.V ----
    if (ntm == 2) attn_tail2(s, g, lane, rowH, nOth, cEgo, egoAct);
    else          attn_tail4(s, g, lane, rowH, nOth, cEgo, egoAct, uniformF);
    __syncthreads();

    // ---- PH9: epilogue (out @ Wc + ego) * 0.5, split across 128 thr ----
    {
        const int half = tid >> 6, d = tid & 63;
        const int kp0 = half * 16;
        float a0 = 0.f, a1 = 0.f;
        #pragma unroll 8
        for (int kp = kp0; kp < kp0 + 16; kp++) {
            float2 wv = __half22float2(__ldg(&dWcp[kp * 64 + d]));
            float2 ov = *reinterpret_cast<const float2*>(&s.sO[2 * kp]);
            a0 += ov.x * wv.x;
            a1 += ov.y * wv.y;
        }
        s.sPar[tid] = a0 + a1;
        __syncthreads();
        if (tid < 64)
            out[b * 64 + tid] =
                ((s.sPar[tid] + s.sPar[64 + tid]) + s.sEgo[tid]) * 0.5f;
    }
}

extern "C" void kernel_launch(void* const* d_in, const int* in_sizes, int n_in,
                              void* d_out, int out_size) {
    (void)in_sizes; (void)n_in; (void)out_size;
    const float* x      = (const float*)d_in[0];
    const float* ego_w0 = (const float*)d_in[1];
    const float* ego_b0 = (const float*)d_in[2];
    const float* ego_w1 = (const float*)d_in[3];
    const float* ego_b1 = (const float*)d_in[4];
    const float* oth_w0 = (const float*)d_in[5];
    const float* oth_b0 = (const float*)d_in[6];
    const float* oth_w1 = (const float*)d_in[7];
    const float* oth_b1 = (const float*)d_in[8];
    const float* Wk     = (const float*)d_in[9];
    const float* Wv     = (const float*)d_in[10];
    const float* Wq     = (const float*)d_in[11];
    const float* Wc     = (const float*)d_in[12];
    float* out = (float*)d_out;

    prep_weights<<<8, 256>>>(oth_w0, oth_w1, Wk, Wv, ego_w1, Wq, Wc);
    ego_attn_kernel<<<8192, NTHR>>>(x, ego_w0, ego_b0, ego_b1,
                                    oth_b0, oth_b1, out);
}